// round 2
// baseline (speedup 1.0000x reference)
#include <cuda_runtime.h>
#include <cuda_bf16.h>

// Sliding-window unfold: out[b, i, j] = x[b, i + j]
//   x:   [B=128, L=8192]  float32
//   out: [B=128, NWIN=8162, W=31] float32
//
// Pure store-bandwidth problem (~130 MB out, 4 MB in; input fully L2/L1
// resident). One thread = 4 consecutive flat output elements = one aligned
// STG.128. Flat chunking keeps every float4 16B-aligned and tail-free
// (TOTAL divisible by 4); per-batch chunking would not be aligned
// (ROW = 253022 ≡ 2 mod 4).

static constexpr unsigned Bv    = 128u;
static constexpr unsigned Lv    = 8192u;
static constexpr unsigned Wv    = 31u;
static constexpr unsigned Rv    = Wv / 2u;           // 15
static constexpr unsigned NWIN  = Lv - 2u * Rv;      // 8162
static constexpr unsigned ROW   = NWIN * Wv;         // 253022
static constexpr unsigned TOTAL = Bv * ROW;          // 32,386,816
static constexpr unsigned CHUNKS = TOTAL / 4u;       // 8,096,704 (exact, no tail)

__global__ void __launch_bounds__(256)
WindowAlignmentLayer_65876208386448_kernel(const float* __restrict__ x,
                                           float* __restrict__ out) {
    unsigned t = blockIdx.x * blockDim.x + threadIdx.x;
    if (t >= CHUNKS) return;

    unsigned o   = t * 4u;
    unsigned b   = o / ROW;            // magic-multiply, constant divisor
    unsigned rem = o - b * ROW;
    unsigned i   = rem / Wv;           // magic-multiply
    unsigned j   = rem - i * Wv;

    const float* __restrict__ xrow = x + (size_t)b * Lv;

    float4 o4;

    if (__builtin_expect(rem > ROW - 4u, 0)) {
        // Cold path: chunk straddles a batch-row boundary (at most 1 element
        // layout; rem == ROW-2 is the only reachable straddle shape).
        float v[4];
#pragma unroll
        for (int k = 0; k < 4; ++k) {
            unsigned rk = rem + (unsigned)k;
            const float* __restrict__ xr = xrow;
            unsigned src;
            if (rk >= ROW) {                 // spills into next batch
                xr  = xrow + Lv;
                src = rk - ROW;              // < 4 -> i'=0, j'=src
            } else {
                unsigned jk = j + (unsigned)k;
                src = i + jk - (jk >= Wv ? (Wv - 1u) : 0u);
            }
            v[k] = __ldg(xr + src);
        }
        o4.x = v[0]; o4.y = v[1]; o4.z = v[2]; o4.w = v[3];
    } else {
        // Hot path: straight-line. Window wrap (j+k >= W) drops src by W-1.
        unsigned s = i + j;
        float v[4];
#pragma unroll
        for (int k = 0; k < 4; ++k) {
            unsigned jk  = j + (unsigned)k;
            unsigned src = s + (unsigned)k - (jk >= Wv ? (Wv - 1u) : 0u);
            v[k] = __ldg(xrow + src);
        }
        o4.x = v[0]; o4.y = v[1]; o4.z = v[2]; o4.w = v[3];
    }

    *reinterpret_cast<float4*>(out + o) = o4;
}

extern "C" void kernel_launch(void* const* d_in, const int* in_sizes, int n_in,
                              void* d_out, int out_size) {
    (void)in_sizes; (void)n_in; (void)out_size;
    const float* x   = (const float*)d_in[0];
    float*       out = (float*)d_out;

    unsigned blocks = (CHUNKS + 255u) / 256u;   // 31,628
    WindowAlignmentLayer_65876208386448_kernel<<<blocks, 256>>>(x, out);
}